// round 11
// baseline (speedup 1.0000x reference)
#include <cuda_runtime.h>
#include <cuda_bf16.h>
#include <math_constants.h>
#include <cstdint>

// Problem constants
#define NWAY  64
#define KSHOT 16
#define QSHOT 512
#define TOPK  20
#define DIM   768
#define NSUP  (NWAY * KSHOT)   // 1024 support rows
#define NQRY  (NWAY * QSHOT)   // 32768 query rows
#define CAP   384              // max candidates per row

// Scratch (static device globals — allocation-free kernel_launch).
__device__ float g_dist[(size_t)NSUP * NQRY];   // APPROX sims (bf16 tensor path)
__device__ float g_x2[NSUP];
__device__ float g_y2[NQRY];
__device__ float g_y2max;
__device__ float g_thresh[NSUP];                // 20th smallest approx per row
__device__ int   g_cand[NSUP * CAP];
__device__ int   g_cnt[NSUP];
__device__ float g_cexact[NSUP * CAP];          // exact fp32 sims of candidates
__device__ int   g_topk[NSUP * TOPK];

// ---------------------------------------------------------------------------
// Kernel 1: row squared-norm, VF4/IC2 FMA structure (frozen since R7; these
// exact bits feed the reference-matching epilogue).
// ---------------------------------------------------------------------------
template <bool TO_X2>
__global__ __launch_bounds__(256)
void rownorm_kernel(const float* __restrict__ v, int nrows) {
    const int lane = threadIdx.x & 31;
    const int wrp  = threadIdx.x >> 5;
    const int row  = blockIdx.x * 8 + wrp;
    if (row >= nrows) return;

    const float* p = v + (size_t)row * DIM;
    float a = 0.f;
    const int k = lane & 7;
#pragma unroll 8
    for (int i = 0; i < 96; i++) {
        float e = __ldg(p + 8 * i + k);
        if (lane < 8) a = __fmaf_rn(e, e, a);
    }
    const unsigned FULL = 0xFFFFFFFFu;
    const int l = lane & 3;
    float s0 = __shfl_sync(FULL, a, l);
    float s1 = __shfl_sync(FULL, a, l + 4);
    float w  = __fadd_rn(s0, s1);
    float w0 = __shfl_sync(FULL, w, 0);
    float w1 = __shfl_sync(FULL, w, 1);
    float w2 = __shfl_sync(FULL, w, 2);
    float w3 = __shfl_sync(FULL, w, 3);
    if (lane == 0) {
        float r = __fadd_rn(__fadd_rn(w0, w1), __fadd_rn(w2, w3));
        if (TO_X2) g_x2[row] = r; else g_y2[row] = r;
    }
}

// ---------------------------------------------------------------------------
// Kernel 1b: y2max (single block, deterministic, no reset needed).
// ---------------------------------------------------------------------------
__global__ __launch_bounds__(1024)
void y2max_kernel() {
    __shared__ float sm[1024];
    float m = 0.f;
    for (int i = threadIdx.x; i < NQRY; i += 1024) m = fmaxf(m, g_y2[i]);
    sm[threadIdx.x] = m;
    __syncthreads();
    for (int s = 512; s > 0; s >>= 1) {
        if (threadIdx.x < s) sm[threadIdx.x] = fmaxf(sm[threadIdx.x], sm[threadIdx.x + s]);
        __syncthreads();
    }
    if (threadIdx.x == 0) g_y2max = sm[0];
}

// ---------------------------------------------------------------------------
// Kernel 2: APPROX GEMM on tensor cores (bf16 mma.sync m16n8k16, f32 accum).
// approx[m,n] = y2[n] - 2 * (bf16(x) . bf16(y)).  Used only to pick
// candidates; exact values are rescored later.
// CTA 128x128, 8 warps (4M x 2N), warp tile 32x64, K-step 16, double buffer.
// ---------------------------------------------------------------------------
__device__ __forceinline__ uint32_t pk_bf16x2(float x, float y) {
    __nv_bfloat162 h = __float22bfloat162_rn(make_float2(x, y));
    return *reinterpret_cast<uint32_t*>(&h);
}

__device__ __forceinline__ void mma16816(float* c, const uint32_t* a, const uint32_t* b) {
    asm volatile(
        "mma.sync.aligned.m16n8k16.row.col.f32.bf16.bf16.f32 "
        "{%0,%1,%2,%3}, {%4,%5,%6,%7}, {%8,%9}, {%0,%1,%2,%3};"
        : "+f"(c[0]), "+f"(c[1]), "+f"(c[2]), "+f"(c[3])
        : "r"(a[0]), "r"(a[1]), "r"(a[2]), "r"(a[3]), "r"(b[0]), "r"(b[1]));
}

#define APAD 12   // uint32 row pitch (8 kpairs + 4 pad) -> conflict-free frag loads

__global__ __launch_bounds__(256)
void approx_gemm_kernel(const float* __restrict__ A,   // support [NSUP][DIM]
                        const float* __restrict__ B)   // query   [NQRY][DIM]
{
    __shared__ uint32_t As[2][128][APAD];
    __shared__ uint32_t Bs[2][128][APAD];

    const int tid  = threadIdx.x;
    const int lane = tid & 31;
    const int wid  = tid >> 5;
    const int wm   = (wid & 3) * 32;    // warp M offset in tile
    const int wn   = (wid >> 2) * 64;   // warp N offset in tile
    const int m0   = blockIdx.y * 128;
    const int n0   = blockIdx.x * 128;

    // staging: thread -> row r (0..127), half (k 0..7 / 8..15)
    const int r    = tid >> 1;
    const int half = tid & 1;
    const float* Ag = A + (size_t)(m0 + r) * DIM + half * 8;
    const float* Bg = B + (size_t)(n0 + r) * DIM + half * 8;

    float acc[2][8][4];
#pragma unroll
    for (int i = 0; i < 2; i++)
#pragma unroll
        for (int j = 0; j < 8; j++)
#pragma unroll
            for (int q = 0; q < 4; q++) acc[i][j][q] = 0.f;

    float4 fa0, fa1, fb0, fb1;

    // prologue: stage 0
    fa0 = *reinterpret_cast<const float4*>(Ag);
    fa1 = *reinterpret_cast<const float4*>(Ag + 4);
    fb0 = *reinterpret_cast<const float4*>(Bg);
    fb1 = *reinterpret_cast<const float4*>(Bg + 4);
    {
        uint32_t* ar = &As[0][r][half * 4];
        ar[0] = pk_bf16x2(fa0.x, fa0.y); ar[1] = pk_bf16x2(fa0.z, fa0.w);
        ar[2] = pk_bf16x2(fa1.x, fa1.y); ar[3] = pk_bf16x2(fa1.z, fa1.w);
        uint32_t* br = &Bs[0][r][half * 4];
        br[0] = pk_bf16x2(fb0.x, fb0.y); br[1] = pk_bf16x2(fb0.z, fb0.w);
        br[2] = pk_bf16x2(fb1.x, fb1.y); br[3] = pk_bf16x2(fb1.z, fb1.w);
    }
    __syncthreads();

    const int NSTEP = DIM / 16;   // 48
    for (int ks = 0; ks < NSTEP; ks++) {
        const int s = ks & 1;
        const bool more = (ks + 1) < NSTEP;
        if (more) {
            const int ko = (ks + 1) * 16;
            fa0 = *reinterpret_cast<const float4*>(Ag + ko);
            fa1 = *reinterpret_cast<const float4*>(Ag + ko + 4);
            fb0 = *reinterpret_cast<const float4*>(Bg + ko);
            fb1 = *reinterpret_cast<const float4*>(Bg + ko + 4);
        }

        // fragment loads (conflict-free per APAD analysis) + 16 mma
        uint32_t afr[2][4], bfr[8][2];
        const int rg = lane >> 2, cg = lane & 3;
#pragma unroll
        for (int mf = 0; mf < 2; mf++) {
            const int row = wm + mf * 16 + rg;
            afr[mf][0] = As[s][row][cg];
            afr[mf][1] = As[s][row + 8][cg];
            afr[mf][2] = As[s][row][cg + 4];
            afr[mf][3] = As[s][row + 8][cg + 4];
        }
#pragma unroll
        for (int f = 0; f < 8; f++) {
            const int col = wn + f * 8 + rg;
            bfr[f][0] = Bs[s][col][cg];
            bfr[f][1] = Bs[s][col][cg + 4];
        }
#pragma unroll
        for (int mf = 0; mf < 2; mf++)
#pragma unroll
            for (int f = 0; f < 8; f++)
                mma16816(acc[mf][f], afr[mf], bfr[f]);

        if (more) {
            const int ns = s ^ 1;
            uint32_t* ar = &As[ns][r][half * 4];
            ar[0] = pk_bf16x2(fa0.x, fa0.y); ar[1] = pk_bf16x2(fa0.z, fa0.w);
            ar[2] = pk_bf16x2(fa1.x, fa1.y); ar[3] = pk_bf16x2(fa1.z, fa1.w);
            uint32_t* br = &Bs[ns][r][half * 4];
            br[0] = pk_bf16x2(fb0.x, fb0.y); br[1] = pk_bf16x2(fb0.z, fb0.w);
            br[2] = pk_bf16x2(fb1.x, fb1.y); br[3] = pk_bf16x2(fb1.z, fb1.w);
        }
        __syncthreads();
    }

    // epilogue: approx = y2[n] - 2*acc
    const int rg = lane >> 2, cg = lane & 3;
#pragma unroll
    for (int f = 0; f < 8; f++) {
        const int n = n0 + wn + f * 8 + 2 * cg;
        float2 y2p = *reinterpret_cast<const float2*>(&g_y2[n]);
#pragma unroll
        for (int mf = 0; mf < 2; mf++) {
            const int mrow = m0 + wm + mf * 16 + rg;
            float* c = acc[mf][f];
            float2 o0 = make_float2(y2p.x - 2.f * c[0], y2p.y - 2.f * c[1]);
            float2 o1 = make_float2(y2p.x - 2.f * c[2], y2p.y - 2.f * c[3]);
            *reinterpret_cast<float2*>(&g_dist[(size_t)mrow * NQRY + n])       = o0;
            *reinterpret_cast<float2*>(&g_dist[(size_t)(mrow + 8) * NQRY + n]) = o1;
        }
    }
}

// ---------------------------------------------------------------------------
// Kernel 3: per-row top-20 smallest of APPROX sims -> threshold (20th value).
// (proven kernel from R10; now additionally records g_thresh)
// ---------------------------------------------------------------------------
#define TPK_THREADS 256
#define NCAND (TPK_THREADS * TOPK)

__device__ __forceinline__ void tinsert(float v, int id, float* vals, int* idxs) {
    float worst = vals[TOPK - 1];
    if (v > worst) return;
    if (v == worst && id > idxs[TOPK - 1]) return;
    int j = TOPK - 1;
    while (j > 0 && (vals[j - 1] > v || (vals[j - 1] == v && idxs[j - 1] > id))) {
        vals[j] = vals[j - 1]; idxs[j] = idxs[j - 1]; --j;
    }
    vals[j] = v; idxs[j] = id;
}

__global__ __launch_bounds__(TPK_THREADS)
void topk_kernel() {
    __shared__ float sv[NCAND];
    __shared__ int   si[NCAND];
    __shared__ float rv[TPK_THREADS];
    __shared__ int   ri[TPK_THREADS];

    const int row = blockIdx.x;
    const int t   = threadIdx.x;
    const float4* d = reinterpret_cast<const float4*>(g_dist + (size_t)row * NQRY);

    float vals[TOPK]; int idxs[TOPK];
#pragma unroll
    for (int j = 0; j < TOPK; j++) { vals[j] = CUDART_INF_F; idxs[j] = 0x7FFFFFFF; }

    for (int i = t; i < NQRY / 4; i += TPK_THREADS) {
        float4 v = d[i];
        int base = i * 4;
        tinsert(v.x, base + 0, vals, idxs);
        tinsert(v.y, base + 1, vals, idxs);
        tinsert(v.z, base + 2, vals, idxs);
        tinsert(v.w, base + 3, vals, idxs);
    }
#pragma unroll
    for (int j = 0; j < TOPK; j++) { sv[t * TOPK + j] = vals[j]; si[t * TOPK + j] = idxs[j]; }
    __syncthreads();

    for (int r = 0; r < TOPK; r++) {
        float bv = CUDART_INF_F; int bi = 0x7FFFFFFF;
        for (int j = t; j < NCAND; j += TPK_THREADS) {
            float v = sv[j]; int id = si[j];
            if (v < bv || (v == bv && id < bi)) { bv = v; bi = id; }
        }
        rv[t] = bv; ri[t] = bi;
        __syncthreads();
        for (int s = TPK_THREADS / 2; s > 0; s >>= 1) {
            if (t < s) {
                if (rv[t + s] < rv[t] || (rv[t + s] == rv[t] && ri[t + s] < ri[t])) {
                    rv[t] = rv[t + s]; ri[t] = ri[t + s];
                }
            }
            __syncthreads();
        }
        if (t == 0 && r == TOPK - 1) g_thresh[row] = rv[0];
        int w = ri[0];
        __syncthreads();
        for (int j = t; j < NCAND; j += TPK_THREADS)
            if (si[j] == w) { sv[j] = CUDART_INF_F; si[j] = 0x7FFFFFFF; }
        __syncthreads();
    }
}

// ---------------------------------------------------------------------------
// Kernel 4: candidate collection. approx <= thresh + margin, margin = 2*eps,
// eps = 2^-6 * sqrt(x2*y2max) (Cauchy-Schwarz bf16 bound) + slack.
// ---------------------------------------------------------------------------
__global__ __launch_bounds__(256)
void scan_kernel() {
    __shared__ int c;
    const int row = blockIdx.x;
    const int t   = threadIdx.x;
    if (t == 0) c = 0;
    __syncthreads();
    const float thr = g_thresh[row] + 0.03125f * sqrtf(g_x2[row] * g_y2max) + 0.05f;
    const float* d = g_dist + (size_t)row * NQRY;
    for (int m = t; m < NQRY; m += 256) {
        if (d[m] <= thr) {
            int p = atomicAdd(&c, 1);
            if (p < CAP) g_cand[row * CAP + p] = m;
        }
    }
    __syncthreads();
    if (t == 0) g_cnt[row] = (c < CAP) ? c : CAP;
}

// ---------------------------------------------------------------------------
// Kernel 5: exact rescore. One thread per candidate replays the EXACT
// ascending-k single-FMA chain + reference epilogue (bit-identical to the
// R10 GEMM per-output arithmetic).
// ---------------------------------------------------------------------------
__global__ __launch_bounds__(CAP)
void rescore_kernel(const float* __restrict__ A, const float* __restrict__ B) {
    const int row = blockIdx.x;
    const int j   = threadIdx.x;
    if (j >= g_cnt[row]) return;
    const int m = g_cand[row * CAP + j];
    const float* a = A + (size_t)row * DIM;
    const float* b = B + (size_t)m * DIM;
    float acc = 0.f;
#pragma unroll 8
    for (int k = 0; k < DIM; k++)
        acc = __fmaf_rn(__ldg(a + k), __ldg(b + k), acc);
    float t = __fadd_rn(g_x2[row], g_y2[m]);
    float u = __fmul_rn(2.0f, acc);
    g_cexact[row * CAP + j] = __fadd_rn(t, -u);
}

// ---------------------------------------------------------------------------
// Kernel 6: final select. Rank-sort candidates by (exact asc, idx asc) —
// identical order to R10's topk — take 20, then apply R10's fp64-DESC tie
// refine verbatim, write g_topk.
// ---------------------------------------------------------------------------
__global__ __launch_bounds__(CAP)
void final_kernel(const float* __restrict__ A, const float* __restrict__ B) {
    __shared__ float  ev[CAP];
    __shared__ int    ei[CAP];
    __shared__ float  s20v[TOPK];
    __shared__ int    s20i[TOPK];
    __shared__ double s20d[TOPK];

    const int row = blockIdx.x;
    const int t   = threadIdx.x;
    const int cnt = g_cnt[row];

    if (t < cnt) { ev[t] = g_cexact[row * CAP + t]; ei[t] = g_cand[row * CAP + t]; }
    __syncthreads();

    if (t < cnt) {
        const float v = ev[t]; const int id = ei[t];
        int rk = 0;
        for (int j = 0; j < cnt; j++)
            rk += (ev[j] < v || (ev[j] == v && ei[j] < id)) ? 1 : 0;
        if (rk < TOPK) { s20v[rk] = v; s20i[rk] = id; }
    }
    __syncthreads();

    // fp64 exact distances for the selected 20 (warp 0)
    if (t < 32) {
        const float* a = A + (size_t)row * DIM;
        for (int j = 0; j < TOPK; j++) {
            const float* b = B + (size_t)s20i[j] * DIM;
            double s = 0.0;
            for (int k = t; k < DIM; k += 32) {
                double diff = (double)a[k] - (double)b[k];
                s += diff * diff;
            }
#pragma unroll
            for (int o = 16; o > 0; o >>= 1)
                s += __shfl_down_sync(0xFFFFFFFFu, s, o);
            if (t == 0) s20d[j] = s;
            __syncwarp();
        }
    }
    __syncthreads();

    if (t == 0) {
        // stable insertion sort by (fp32 asc, fp64 exact DESC, idx asc)
        for (int i = 1; i < TOPK; i++) {
            float v = s20v[i]; double e = s20d[i]; int id = s20i[i];
            int j = i - 1;
            while (j >= 0 && (s20v[j] > v ||
                   (s20v[j] == v && (s20d[j] < e ||
                    (s20d[j] == e && s20i[j] > id))))) {
                s20v[j + 1] = s20v[j]; s20d[j + 1] = s20d[j]; s20i[j + 1] = s20i[j];
                --j;
            }
            s20v[j + 1] = v; s20d[j + 1] = e; s20i[j + 1] = id;
        }
        for (int i = 0; i < TOPK; i++) g_topk[row * TOPK + i] = s20i[i];
    }
}

// ---------------------------------------------------------------------------
// Kernel 7: gather selected query rows.
// ---------------------------------------------------------------------------
__global__ void gather_kernel(const float* __restrict__ q, float* __restrict__ out) {
    const int pair = blockIdx.x;
    const int idx  = g_topk[pair];
    const float4* src = reinterpret_cast<const float4*>(q + (size_t)idx * DIM);
    float4* dst = reinterpret_cast<float4*>(out + (size_t)pair * DIM);
    dst[threadIdx.x] = src[threadIdx.x];
}

// ---------------------------------------------------------------------------
// Kernel 8: accuracy scalar.
// ---------------------------------------------------------------------------
__global__ void acc_kernel(float* __restrict__ out, int out_size) {
    __shared__ int cnt[256];
    const int t = threadIdx.x;
    int c = 0;
    for (int j = t; j < NSUP * TOPK; j += 256) {
        int row = j / TOPK;
        int idx = g_topk[j];
        c += ((idx / QSHOT) == (row / KSHOT)) ? 1 : 0;
    }
    cnt[t] = c;
    __syncthreads();
    for (int s = 128; s > 0; s >>= 1) { if (t < s) cnt[t] += cnt[t + s]; __syncthreads(); }
    if (t == 0) {
        const int total = NSUP * TOPK * DIM;
        if (out_size > total)
            out[total] = __fdiv_rn((float)cnt[0], (float)(NSUP * TOPK));
    }
}

// ---------------------------------------------------------------------------
extern "C" void kernel_launch(void* const* d_in, const int* in_sizes, int n_in,
                              void* d_out, int out_size) {
    const float* support = (const float*)d_in[0];
    const float* query   = (const float*)d_in[1];
    if (n_in >= 2 && in_sizes[0] != NSUP * DIM) {
        support = (const float*)d_in[1];
        query   = (const float*)d_in[0];
    }
    float* out = (float*)d_out;

    rownorm_kernel<true ><<<NSUP / 8, 256>>>(support, NSUP);
    rownorm_kernel<false><<<NQRY / 8, 256>>>(query,   NQRY);
    y2max_kernel<<<1, 1024>>>();
    {
        dim3 grid(NQRY / 128, NSUP / 128);   // (256, 8)
        approx_gemm_kernel<<<grid, 256>>>(support, query);
    }
    topk_kernel<<<NSUP, TPK_THREADS>>>();
    scan_kernel<<<NSUP, 256>>>();
    rescore_kernel<<<NSUP, CAP>>>(support, query);
    final_kernel<<<NSUP, CAP>>>(support, query);
    gather_kernel<<<NSUP * TOPK, DIM / 4>>>(query, out);
    acc_kernel<<<1, 256>>>(out, out_size);
}

// round 12
// speedup vs baseline: 1.2010x; 1.2010x over previous
#include <cuda_runtime.h>
#include <cuda_bf16.h>
#include <math_constants.h>
#include <cstdint>

// Problem constants
#define NWAY  64
#define KSHOT 16
#define QSHOT 512
#define TOPK  20
#define DIM   768
#define NSUP  (NWAY * KSHOT)   // 1024 support rows
#define NQRY  (NWAY * QSHOT)   // 32768 query rows
#define CAP   512              // max candidates per row (smem u16 list)

// Scratch (static device globals — allocation-free kernel_launch).
__device__ float g_dist[(size_t)NSUP * NQRY];   // APPROX sims (bf16 tensor path)
__device__ float g_x2[NSUP];
__device__ float g_y2[NQRY];
__device__ int   g_y2max_i;                     // bit-pattern max of y2 (atomicMax, idempotent)
__device__ int   g_topk[NSUP * TOPK];

// ---------------------------------------------------------------------------
// Kernel 1: row squared-norm, VF4/IC2 FMA structure (frozen since R7).
// Query variant also maintains g_y2max_i via atomicMax on the positive-float
// bit pattern (order-independent & idempotent across graph replays).
// ---------------------------------------------------------------------------
template <bool TO_X2>
__global__ __launch_bounds__(256)
void rownorm_kernel(const float* __restrict__ v, int nrows) {
    const int lane = threadIdx.x & 31;
    const int wrp  = threadIdx.x >> 5;
    const int row  = blockIdx.x * 8 + wrp;
    if (row >= nrows) return;

    const float* p = v + (size_t)row * DIM;
    float a = 0.f;
    const int k = lane & 7;
#pragma unroll 8
    for (int i = 0; i < 96; i++) {
        float e = __ldg(p + 8 * i + k);
        if (lane < 8) a = __fmaf_rn(e, e, a);
    }
    const unsigned FULL = 0xFFFFFFFFu;
    const int l = lane & 3;
    float s0 = __shfl_sync(FULL, a, l);
    float s1 = __shfl_sync(FULL, a, l + 4);
    float w  = __fadd_rn(s0, s1);
    float w0 = __shfl_sync(FULL, w, 0);
    float w1 = __shfl_sync(FULL, w, 1);
    float w2 = __shfl_sync(FULL, w, 2);
    float w3 = __shfl_sync(FULL, w, 3);
    if (lane == 0) {
        float r = __fadd_rn(__fadd_rn(w0, w1), __fadd_rn(w2, w3));
        if (TO_X2) {
            g_x2[row] = r;
        } else {
            g_y2[row] = r;
            atomicMax(&g_y2max_i, __float_as_int(r));
        }
    }
}

// ---------------------------------------------------------------------------
// Kernel 2: APPROX GEMM on tensor cores (bf16 mma.sync m16n8k16, f32 accum).
// (unchanged from R11; measured 374us)
// ---------------------------------------------------------------------------
__device__ __forceinline__ uint32_t pk_bf16x2(float x, float y) {
    __nv_bfloat162 h = __float22bfloat162_rn(make_float2(x, y));
    return *reinterpret_cast<uint32_t*>(&h);
}

__device__ __forceinline__ void mma16816(float* c, const uint32_t* a, const uint32_t* b) {
    asm volatile(
        "mma.sync.aligned.m16n8k16.row.col.f32.bf16.bf16.f32 "
        "{%0,%1,%2,%3}, {%4,%5,%6,%7}, {%8,%9}, {%0,%1,%2,%3};"
        : "+f"(c[0]), "+f"(c[1]), "+f"(c[2]), "+f"(c[3])
        : "r"(a[0]), "r"(a[1]), "r"(a[2]), "r"(a[3]), "r"(b[0]), "r"(b[1]));
}

#define APAD 12

__global__ __launch_bounds__(256)
void approx_gemm_kernel(const float* __restrict__ A,
                        const float* __restrict__ B)
{
    __shared__ uint32_t As[2][128][APAD];
    __shared__ uint32_t Bs[2][128][APAD];

    const int tid  = threadIdx.x;
    const int lane = tid & 31;
    const int wid  = tid >> 5;
    const int wm   = (wid & 3) * 32;
    const int wn   = (wid >> 2) * 64;
    const int m0   = blockIdx.y * 128;
    const int n0   = blockIdx.x * 128;

    const int r    = tid >> 1;
    const int half = tid & 1;
    const float* Ag = A + (size_t)(m0 + r) * DIM + half * 8;
    const float* Bg = B + (size_t)(n0 + r) * DIM + half * 8;

    float acc[2][8][4];
#pragma unroll
    for (int i = 0; i < 2; i++)
#pragma unroll
        for (int j = 0; j < 8; j++)
#pragma unroll
            for (int q = 0; q < 4; q++) acc[i][j][q] = 0.f;

    float4 fa0, fa1, fb0, fb1;

    fa0 = *reinterpret_cast<const float4*>(Ag);
    fa1 = *reinterpret_cast<const float4*>(Ag + 4);
    fb0 = *reinterpret_cast<const float4*>(Bg);
    fb1 = *reinterpret_cast<const float4*>(Bg + 4);
    {
        uint32_t* ar = &As[0][r][half * 4];
        ar[0] = pk_bf16x2(fa0.x, fa0.y); ar[1] = pk_bf16x2(fa0.z, fa0.w);
        ar[2] = pk_bf16x2(fa1.x, fa1.y); ar[3] = pk_bf16x2(fa1.z, fa1.w);
        uint32_t* br = &Bs[0][r][half * 4];
        br[0] = pk_bf16x2(fb0.x, fb0.y); br[1] = pk_bf16x2(fb0.z, fb0.w);
        br[2] = pk_bf16x2(fb1.x, fb1.y); br[3] = pk_bf16x2(fb1.z, fb1.w);
    }
    __syncthreads();

    const int NSTEP = DIM / 16;
    for (int ks = 0; ks < NSTEP; ks++) {
        const int s = ks & 1;
        const bool more = (ks + 1) < NSTEP;
        if (more) {
            const int ko = (ks + 1) * 16;
            fa0 = *reinterpret_cast<const float4*>(Ag + ko);
            fa1 = *reinterpret_cast<const float4*>(Ag + ko + 4);
            fb0 = *reinterpret_cast<const float4*>(Bg + ko);
            fb1 = *reinterpret_cast<const float4*>(Bg + ko + 4);
        }

        uint32_t afr[2][4], bfr[8][2];
        const int rg = lane >> 2, cg = lane & 3;
#pragma unroll
        for (int mf = 0; mf < 2; mf++) {
            const int row = wm + mf * 16 + rg;
            afr[mf][0] = As[s][row][cg];
            afr[mf][1] = As[s][row + 8][cg];
            afr[mf][2] = As[s][row][cg + 4];
            afr[mf][3] = As[s][row + 8][cg + 4];
        }
#pragma unroll
        for (int f = 0; f < 8; f++) {
            const int col = wn + f * 8 + rg;
            bfr[f][0] = Bs[s][col][cg];
            bfr[f][1] = Bs[s][col][cg + 4];
        }
#pragma unroll
        for (int mf = 0; mf < 2; mf++)
#pragma unroll
            for (int f = 0; f < 8; f++)
                mma16816(acc[mf][f], afr[mf], bfr[f]);

        if (more) {
            const int ns = s ^ 1;
            uint32_t* ar = &As[ns][r][half * 4];
            ar[0] = pk_bf16x2(fa0.x, fa0.y); ar[1] = pk_bf16x2(fa0.z, fa0.w);
            ar[2] = pk_bf16x2(fa1.x, fa1.y); ar[3] = pk_bf16x2(fa1.z, fa1.w);
            uint32_t* br = &Bs[ns][r][half * 4];
            br[0] = pk_bf16x2(fb0.x, fb0.y); br[1] = pk_bf16x2(fb0.z, fb0.w);
            br[2] = pk_bf16x2(fb1.x, fb1.y); br[3] = pk_bf16x2(fb1.z, fb1.w);
        }
        __syncthreads();
    }

    const int rg = lane >> 2, cg = lane & 3;
#pragma unroll
    for (int f = 0; f < 8; f++) {
        const int n = n0 + wn + f * 8 + 2 * cg;
        float2 y2p = *reinterpret_cast<const float2*>(&g_y2[n]);
#pragma unroll
        for (int mf = 0; mf < 2; mf++) {
            const int mrow = m0 + wm + mf * 16 + rg;
            float* c = acc[mf][f];
            float2 o0 = make_float2(y2p.x - 2.f * c[0], y2p.y - 2.f * c[1]);
            float2 o1 = make_float2(y2p.x - 2.f * c[2], y2p.y - 2.f * c[3]);
            *reinterpret_cast<float2*>(&g_dist[(size_t)mrow * NQRY + n])       = o0;
            *reinterpret_cast<float2*>(&g_dist[(size_t)(mrow + 8) * NQRY + n]) = o1;
        }
    }
}

// ---------------------------------------------------------------------------
// Kernel 3 (FUSED): per-row threshold (20th smallest approx) -> candidate
// collection -> exact fp32 rescore (bit-exact ascending-k chain) -> final
// rank-select -> fp64-DESC tie refine -> g_topk.  One block per row.
// ---------------------------------------------------------------------------
#define SEL_THREADS 256
#define POOL (SEL_THREADS * TOPK)   // 5120

__device__ __forceinline__ void tinsert(float v, int id, float* vals, int* idxs) {
    float worst = vals[TOPK - 1];
    if (v > worst) return;
    if (v == worst && id > idxs[TOPK - 1]) return;
    int j = TOPK - 1;
    while (j > 0 && (vals[j - 1] > v || (vals[j - 1] == v && idxs[j - 1] > id))) {
        vals[j] = vals[j - 1]; idxs[j] = idxs[j - 1]; --j;
    }
    vals[j] = v; idxs[j] = id;
}

__global__ __launch_bounds__(SEL_THREADS)
void select_kernel(const float* __restrict__ A, const float* __restrict__ B) {
    __shared__ float          sv[POOL];       // 20480 B
    __shared__ unsigned short si[POOL];       // 10240 B
    __shared__ float          rv[SEL_THREADS];
    __shared__ int            ri[SEL_THREADS];
    __shared__ float          s_arow[DIM];    // 3072 B
    __shared__ unsigned short scand[CAP];     // 1024 B
    __shared__ float          scex[CAP];      // 2048 B
    __shared__ float          s20v[TOPK];
    __shared__ int            s20i[TOPK];
    __shared__ double         s20d[TOPK];
    __shared__ int            s_cnt;
    __shared__ float          s_thr;

    const int row = blockIdx.x;
    const int t   = threadIdx.x;
    const float* drow = g_dist + (size_t)row * NQRY;

    // ---- Phase A: per-thread top-20 over strided float4 chunks ----
    {
        const float4* d4 = reinterpret_cast<const float4*>(drow);
        float vals[TOPK]; int idxs[TOPK];
#pragma unroll
        for (int j = 0; j < TOPK; j++) { vals[j] = CUDART_INF_F; idxs[j] = 0x7FFFFFFF; }
        for (int i = t; i < NQRY / 4; i += SEL_THREADS) {
            float4 v = d4[i];
            int base = i * 4;
            tinsert(v.x, base + 0, vals, idxs);
            tinsert(v.y, base + 1, vals, idxs);
            tinsert(v.z, base + 2, vals, idxs);
            tinsert(v.w, base + 3, vals, idxs);
        }
#pragma unroll
        for (int j = 0; j < TOPK; j++) {
            sv[t * TOPK + j] = vals[j];
            si[t * TOPK + j] = (idxs[j] == 0x7FFFFFFF) ? 0xFFFFu : (unsigned short)idxs[j];
        }
    }
    __syncthreads();

    // ---- Phase B: 20 eviction rounds -> a20 (20th smallest approx) ----
    float a20 = 0.f;
    for (int r = 0; r < TOPK; r++) {
        float bv = CUDART_INF_F; int bi = 0x7FFFFFFF;
        for (int j = t; j < POOL; j += SEL_THREADS) {
            float v = sv[j]; int id = si[j];
            if (v < bv || (v == bv && id < bi)) { bv = v; bi = id; }
        }
        rv[t] = bv; ri[t] = bi;
        __syncthreads();
        for (int s = SEL_THREADS / 2; s > 0; s >>= 1) {
            if (t < s) {
                if (rv[t + s] < rv[t] || (rv[t + s] == rv[t] && ri[t + s] < ri[t])) {
                    rv[t] = rv[t + s]; ri[t] = ri[t + s];
                }
            }
            __syncthreads();
        }
        a20 = rv[0];
        int w = ri[0];
        __syncthreads();
        if (r < TOPK - 1) {
            for (int j = t; j < POOL; j += SEL_THREADS)
                if (si[j] == (unsigned short)w && sv[j] == a20) {
                    sv[j] = CUDART_INF_F; si[j] = 0xFFFFu;
                }
            __syncthreads();
        }
    }

    // ---- Phase C: threshold + stage support row + collect candidates ----
    if (t == 0) {
        float y2max = __int_as_float(g_y2max_i);
        s_thr = a20 + 0.03125f * sqrtf(g_x2[row] * y2max) + 0.05f;
        s_cnt = 0;
    }
    {
        const float4* a4 = reinterpret_cast<const float4*>(A + (size_t)row * DIM);
        if (t < DIM / 4)
            *reinterpret_cast<float4*>(&s_arow[t * 4]) = a4[t];
    }
    __syncthreads();

    {
        const float thr = s_thr;
        for (int m = t; m < NQRY; m += SEL_THREADS) {
            if (drow[m] <= thr) {
                int p = atomicAdd(&s_cnt, 1);
                if (p < CAP) scand[p] = (unsigned short)m;
            }
        }
    }
    __syncthreads();
    const int cnt = (s_cnt < CAP) ? s_cnt : CAP;

    // ---- Phase D: exact fp32 rescore (register-double-buffered float4 chain,
    //      ascending-k single-FMA accumulation == reference GEMM bits) ----
    const float x2row = g_x2[row];
    for (int j = t; j < cnt; j += SEL_THREADS) {
        const int m = scand[j];
        const float4* b4 = reinterpret_cast<const float4*>(B + (size_t)m * DIM);
        float acc = 0.f;
        float4 cur = __ldg(b4);
#pragma unroll 4
        for (int i = 0; i < DIM / 4; i++) {
            float4 nxt = make_float4(0.f, 0.f, 0.f, 0.f);
            if (i + 1 < DIM / 4) nxt = __ldg(b4 + i + 1);
            float4 av = *reinterpret_cast<const float4*>(&s_arow[4 * i]);
            acc = __fmaf_rn(av.x, cur.x, acc);
            acc = __fmaf_rn(av.y, cur.y, acc);
            acc = __fmaf_rn(av.z, cur.z, acc);
            acc = __fmaf_rn(av.w, cur.w, acc);
            cur = nxt;
        }
        float tt = __fadd_rn(x2row, g_y2[m]);
        float uu = __fmul_rn(2.0f, acc);
        scex[j] = __fadd_rn(tt, -uu);
    }
    __syncthreads();

    // ---- Phase E: rank-select 20 by (exact asc, idx asc) ----
    for (int j = t; j < cnt; j += SEL_THREADS) {
        const float v = scex[j]; const int id = scand[j];
        int rk = 0;
        for (int q = 0; q < cnt; q++)
            rk += (scex[q] < v || (scex[q] == v && (int)scand[q] < id)) ? 1 : 0;
        if (rk < TOPK) { s20v[rk] = v; s20i[rk] = id; }
    }
    __syncthreads();

    // ---- Phase F: fp64 exact distances + anti-exact tie refine ----
    if (t < 32) {
        for (int j = 0; j < TOPK; j++) {
            const float* b = B + (size_t)s20i[j] * DIM;
            double s = 0.0;
            for (int k = t; k < DIM; k += 32) {
                double diff = (double)s_arow[k] - (double)b[k];
                s += diff * diff;
            }
#pragma unroll
            for (int o = 16; o > 0; o >>= 1)
                s += __shfl_down_sync(0xFFFFFFFFu, s, o);
            if (t == 0) s20d[j] = s;
            __syncwarp();
        }
    }
    __syncthreads();

    if (t == 0) {
        // stable insertion sort by (fp32 asc, fp64 exact DESC, idx asc)
        for (int i = 1; i < TOPK; i++) {
            float v = s20v[i]; double e = s20d[i]; int id = s20i[i];
            int j = i - 1;
            while (j >= 0 && (s20v[j] > v ||
                   (s20v[j] == v && (s20d[j] < e ||
                    (s20d[j] == e && s20i[j] > id))))) {
                s20v[j + 1] = s20v[j]; s20d[j + 1] = s20d[j]; s20i[j + 1] = s20i[j];
                --j;
            }
            s20v[j + 1] = v; s20d[j + 1] = e; s20i[j + 1] = id;
        }
        for (int i = 0; i < TOPK; i++) g_topk[row * TOPK + i] = s20i[i];
    }
}

// ---------------------------------------------------------------------------
// Kernel 4: gather selected query rows.
// ---------------------------------------------------------------------------
__global__ void gather_kernel(const float* __restrict__ q, float* __restrict__ out) {
    const int pair = blockIdx.x;
    const int idx  = g_topk[pair];
    const float4* src = reinterpret_cast<const float4*>(q + (size_t)idx * DIM);
    float4* dst = reinterpret_cast<float4*>(out + (size_t)pair * DIM);
    dst[threadIdx.x] = src[threadIdx.x];
}

// ---------------------------------------------------------------------------
// Kernel 5: accuracy scalar.
// ---------------------------------------------------------------------------
__global__ void acc_kernel(float* __restrict__ out, int out_size) {
    __shared__ int cnt[256];
    const int t = threadIdx.x;
    int c = 0;
    for (int j = t; j < NSUP * TOPK; j += 256) {
        int row = j / TOPK;
        int idx = g_topk[j];
        c += ((idx / QSHOT) == (row / KSHOT)) ? 1 : 0;
    }
    cnt[t] = c;
    __syncthreads();
    for (int s = 128; s > 0; s >>= 1) { if (t < s) cnt[t] += cnt[t + s]; __syncthreads(); }
    if (t == 0) {
        const int total = NSUP * TOPK * DIM;
        if (out_size > total)
            out[total] = __fdiv_rn((float)cnt[0], (float)(NSUP * TOPK));
    }
}

// ---------------------------------------------------------------------------
extern "C" void kernel_launch(void* const* d_in, const int* in_sizes, int n_in,
                              void* d_out, int out_size) {
    const float* support = (const float*)d_in[0];
    const float* query   = (const float*)d_in[1];
    if (n_in >= 2 && in_sizes[0] != NSUP * DIM) {
        support = (const float*)d_in[1];
        query   = (const float*)d_in[0];
    }
    float* out = (float*)d_out;

    rownorm_kernel<true ><<<NSUP / 8, 256>>>(support, NSUP);
    rownorm_kernel<false><<<NQRY / 8, 256>>>(query,   NQRY);
    {
        dim3 grid(NQRY / 128, NSUP / 128);   // (256, 8)
        approx_gemm_kernel<<<grid, 256>>>(support, query);
    }
    select_kernel<<<NSUP, SEL_THREADS>>>(support, query);
    gather_kernel<<<NSUP * TOPK, DIM / 4>>>(query, out);
    acc_kernel<<<1, 256>>>(out, out_size);
}

// round 15
// speedup vs baseline: 4.5929x; 3.8243x over previous
#include <cuda_runtime.h>
#include <cuda_bf16.h>
#include <math_constants.h>
#include <cstdint>

// Problem constants
#define NWAY  64
#define KSHOT 16
#define QSHOT 512
#define TOPK  20
#define DIM   768
#define NSUP  (NWAY * KSHOT)   // 1024 support rows
#define NQRY  (NWAY * QSHOT)   // 32768 query rows
#define CAP   1024             // max candidates per row
#define HSHIFT 16              // histogram key shift: bin = 2^16 ulp (~4 units
                               // at the 512-1024 binade) -> 255 bins cover
                               // ~1000 units from row min (R14 used 13 -> only
                               // ~127 units; outlier-min rows overflowed it)

// Scratch (static device globals — allocation-free kernel_launch).
__device__ float g_dist[(size_t)NSUP * NQRY];   // APPROX sims (bf16 tensor path)
__device__ float g_x2[NSUP];
__device__ float g_y2[NQRY];
__device__ int   g_y2max_i;                     // bit-pattern max of y2 (atomicMax, idempotent)
__device__ int   g_topk[NSUP * TOPK];

// ---------------------------------------------------------------------------
// Kernel 1: row squared-norm, VF4/IC2 FMA structure (frozen since R7).
// ---------------------------------------------------------------------------
template <bool TO_X2>
__global__ __launch_bounds__(256)
void rownorm_kernel(const float* __restrict__ v, int nrows) {
    const int lane = threadIdx.x & 31;
    const int wrp  = threadIdx.x >> 5;
    const int row  = blockIdx.x * 8 + wrp;
    if (row >= nrows) return;

    const float* p = v + (size_t)row * DIM;
    float a = 0.f;
    const int k = lane & 7;
#pragma unroll 8
    for (int i = 0; i < 96; i++) {
        float e = __ldg(p + 8 * i + k);
        if (lane < 8) a = __fmaf_rn(e, e, a);
    }
    const unsigned FULL = 0xFFFFFFFFu;
    const int l = lane & 3;
    float s0 = __shfl_sync(FULL, a, l);
    float s1 = __shfl_sync(FULL, a, l + 4);
    float w  = __fadd_rn(s0, s1);
    float w0 = __shfl_sync(FULL, w, 0);
    float w1 = __shfl_sync(FULL, w, 1);
    float w2 = __shfl_sync(FULL, w, 2);
    float w3 = __shfl_sync(FULL, w, 3);
    if (lane == 0) {
        float r = __fadd_rn(__fadd_rn(w0, w1), __fadd_rn(w2, w3));
        if (TO_X2) {
            g_x2[row] = r;
        } else {
            g_y2[row] = r;
            atomicMax(&g_y2max_i, __float_as_int(r));
        }
    }
}

// ---------------------------------------------------------------------------
// Kernel 2: APPROX GEMM on tensor cores (bf16 mma.sync m16n8k16, f32 accum).
// (unchanged; measured 374us in R11)
// ---------------------------------------------------------------------------
__device__ __forceinline__ uint32_t pk_bf16x2(float x, float y) {
    __nv_bfloat162 h = __float22bfloat162_rn(make_float2(x, y));
    return *reinterpret_cast<uint32_t*>(&h);
}

__device__ __forceinline__ void mma16816(float* c, const uint32_t* a, const uint32_t* b) {
    asm volatile(
        "mma.sync.aligned.m16n8k16.row.col.f32.bf16.bf16.f32 "
        "{%0,%1,%2,%3}, {%4,%5,%6,%7}, {%8,%9}, {%0,%1,%2,%3};"
        : "+f"(c[0]), "+f"(c[1]), "+f"(c[2]), "+f"(c[3])
        : "r"(a[0]), "r"(a[1]), "r"(a[2]), "r"(a[3]), "r"(b[0]), "r"(b[1]));
}

#define APAD 12

__global__ __launch_bounds__(256)
void approx_gemm_kernel(const float* __restrict__ A,
                        const float* __restrict__ B)
{
    __shared__ uint32_t As[2][128][APAD];
    __shared__ uint32_t Bs[2][128][APAD];

    const int tid  = threadIdx.x;
    const int lane = tid & 31;
    const int wid  = tid >> 5;
    const int wm   = (wid & 3) * 32;
    const int wn   = (wid >> 2) * 64;
    const int m0   = blockIdx.y * 128;
    const int n0   = blockIdx.x * 128;

    const int r    = tid >> 1;
    const int half = tid & 1;
    const float* Ag = A + (size_t)(m0 + r) * DIM + half * 8;
    const float* Bg = B + (size_t)(n0 + r) * DIM + half * 8;

    float acc[2][8][4];
#pragma unroll
    for (int i = 0; i < 2; i++)
#pragma unroll
        for (int j = 0; j < 8; j++)
#pragma unroll
            for (int q = 0; q < 4; q++) acc[i][j][q] = 0.f;

    float4 fa0, fa1, fb0, fb1;

    fa0 = *reinterpret_cast<const float4*>(Ag);
    fa1 = *reinterpret_cast<const float4*>(Ag + 4);
    fb0 = *reinterpret_cast<const float4*>(Bg);
    fb1 = *reinterpret_cast<const float4*>(Bg + 4);
    {
        uint32_t* ar = &As[0][r][half * 4];
        ar[0] = pk_bf16x2(fa0.x, fa0.y); ar[1] = pk_bf16x2(fa0.z, fa0.w);
        ar[2] = pk_bf16x2(fa1.x, fa1.y); ar[3] = pk_bf16x2(fa1.z, fa1.w);
        uint32_t* br = &Bs[0][r][half * 4];
        br[0] = pk_bf16x2(fb0.x, fb0.y); br[1] = pk_bf16x2(fb0.z, fb0.w);
        br[2] = pk_bf16x2(fb1.x, fb1.y); br[3] = pk_bf16x2(fb1.z, fb1.w);
    }
    __syncthreads();

    const int NSTEP = DIM / 16;
    for (int ks = 0; ks < NSTEP; ks++) {
        const int s = ks & 1;
        const bool more = (ks + 1) < NSTEP;
        if (more) {
            const int ko = (ks + 1) * 16;
            fa0 = *reinterpret_cast<const float4*>(Ag + ko);
            fa1 = *reinterpret_cast<const float4*>(Ag + ko + 4);
            fb0 = *reinterpret_cast<const float4*>(Bg + ko);
            fb1 = *reinterpret_cast<const float4*>(Bg + ko + 4);
        }

        uint32_t afr[2][4], bfr[8][2];
        const int rg = lane >> 2, cg = lane & 3;
#pragma unroll
        for (int mf = 0; mf < 2; mf++) {
            const int rw = wm + mf * 16 + rg;
            afr[mf][0] = As[s][rw][cg];
            afr[mf][1] = As[s][rw + 8][cg];
            afr[mf][2] = As[s][rw][cg + 4];
            afr[mf][3] = As[s][rw + 8][cg + 4];
        }
#pragma unroll
        for (int f = 0; f < 8; f++) {
            const int col = wn + f * 8 + rg;
            bfr[f][0] = Bs[s][col][cg];
            bfr[f][1] = Bs[s][col][cg + 4];
        }
#pragma unroll
        for (int mf = 0; mf < 2; mf++)
#pragma unroll
            for (int f = 0; f < 8; f++)
                mma16816(acc[mf][f], afr[mf], bfr[f]);

        if (more) {
            const int ns = s ^ 1;
            uint32_t* ar = &As[ns][r][half * 4];
            ar[0] = pk_bf16x2(fa0.x, fa0.y); ar[1] = pk_bf16x2(fa0.z, fa0.w);
            ar[2] = pk_bf16x2(fa1.x, fa1.y); ar[3] = pk_bf16x2(fa1.z, fa1.w);
            uint32_t* br = &Bs[ns][r][half * 4];
            br[0] = pk_bf16x2(fb0.x, fb0.y); br[1] = pk_bf16x2(fb0.z, fb0.w);
            br[2] = pk_bf16x2(fb1.x, fb1.y); br[3] = pk_bf16x2(fb1.z, fb1.w);
        }
        __syncthreads();
    }

    const int rg = lane >> 2, cg = lane & 3;
#pragma unroll
    for (int f = 0; f < 8; f++) {
        const int n = n0 + wn + f * 8 + 2 * cg;
        float2 y2p = *reinterpret_cast<const float2*>(&g_y2[n]);
#pragma unroll
        for (int mf = 0; mf < 2; mf++) {
            const int mrow = m0 + wm + mf * 16 + rg;
            float* c = acc[mf][f];
            float2 o0 = make_float2(y2p.x - 2.f * c[0], y2p.y - 2.f * c[1]);
            float2 o1 = make_float2(y2p.x - 2.f * c[2], y2p.y - 2.f * c[3]);
            *reinterpret_cast<float2*>(&g_dist[(size_t)mrow * NQRY + n])       = o0;
            *reinterpret_cast<float2*>(&g_dist[(size_t)(mrow + 8) * NQRY + n]) = o1;
        }
    }
}

// ---------------------------------------------------------------------------
// Total-order float key (monotone over ALL floats incl. negatives) + inverse.
// ---------------------------------------------------------------------------
__device__ __forceinline__ unsigned fkey(float f) {
    unsigned u = __float_as_uint(f);
    return (u & 0x80000000u) ? ~u : (u | 0x80000000u);
}
__device__ __forceinline__ float fkey_inv(unsigned k) {
    unsigned u = (k & 0x80000000u) ? (k & 0x7FFFFFFFu) : ~k;
    return __uint_as_float(u);
}

// ---------------------------------------------------------------------------
// Kernel 3: HISTOGRAM select.
// Per row: (1) vectorized min; (2) 256-bin histogram of fkey>>HSHIFT offset
// from fkey(min)>>HSHIFT (bin ~4 units; 255 bins cover ~1000 units -> any
// min->20th gap); cum>=20 -> bin edge strictly above the 20th-smallest
// approx; (3) collect candidates <= edge + proven bf16 margin; (4) bit-exact
// fp32 rescore; (5) rank-select by (exact asc, idx asc); (6) fp64-DESC tie
// refine.
// ---------------------------------------------------------------------------
#define SEL_THREADS 256

__global__ __launch_bounds__(SEL_THREADS)
void select_kernel(const float* __restrict__ A, const float* __restrict__ B) {
    __shared__ int            s_hist[256];
    __shared__ float          s_arow[DIM];
    __shared__ unsigned short scand[CAP];
    __shared__ float          scex[CAP];
    __shared__ float          s20v[TOPK];
    __shared__ int            s20i[TOPK];
    __shared__ double         s20d[TOPK];
    __shared__ float          s_wmin[8];
    __shared__ int            s_cnt;
    __shared__ float          s_thr;
    __shared__ unsigned       s_bk;

    const int row = blockIdx.x;
    const int t   = threadIdx.x;
    const float* drow = g_dist + (size_t)row * NQRY;
    const float4* d4  = reinterpret_cast<const float4*>(drow);

    if (t < 256) s_hist[t] = 0;
    if (t < TOPK) { s20v[t] = CUDART_INF_F; s20i[t] = 0; }   // crash guard
    if (t < DIM / 4)
        reinterpret_cast<float4*>(s_arow)[t] =
            reinterpret_cast<const float4*>(A + (size_t)row * DIM)[t];

    // ---- pass 1: row min ----
    float mn = CUDART_INF_F;
    for (int i = t; i < NQRY / 4; i += SEL_THREADS) {
        float4 v = d4[i];
        mn = fminf(mn, fminf(fminf(v.x, v.y), fminf(v.z, v.w)));
    }
#pragma unroll
    for (int o = 16; o > 0; o >>= 1)
        mn = fminf(mn, __shfl_xor_sync(0xFFFFFFFFu, mn, o));
    if ((t & 31) == 0) s_wmin[t >> 5] = mn;
    __syncthreads();
    if (t == 0) {
        float m = s_wmin[0];
#pragma unroll
        for (int w = 1; w < 8; w++) m = fminf(m, s_wmin[w]);
        s_bk = fkey(m) >> HSHIFT;
    }
    __syncthreads();
    const unsigned bk = s_bk;

    // ---- pass 2: histogram (values beyond 255 bins are irrelevant; skip) ----
    for (int i = t; i < NQRY / 4; i += SEL_THREADS) {
        float4 v = d4[i];
        float c[4] = {v.x, v.y, v.z, v.w};
#pragma unroll
        for (int q = 0; q < 4; q++) {
            int b = (int)((fkey(c[q]) >> HSHIFT) - bk);
            if ((unsigned)b < 255u) atomicAdd(&s_hist[b], 1);
        }
    }
    __syncthreads();
    if (t == 0) {
        int cum = 0, b20 = 254;
        for (int b = 0; b < 255; b++) {
            cum += s_hist[b];
            if (cum >= TOPK) { b20 = b; break; }
        }
        // edge = float at the key-boundary above bin b20 -> strictly > a20.
        float edge  = fkey_inv((bk + (unsigned)b20 + 1u) << HSHIFT);
        float y2max = __int_as_float(g_y2max_i);
        s_thr = edge + 0.03125f * sqrtf(g_x2[row] * y2max) + 0.05f;
        s_cnt = 0;
    }
    __syncthreads();
    const float thr = s_thr;

    // ---- pass 3: collect candidates ----
    for (int i = t; i < NQRY / 4; i += SEL_THREADS) {
        float4 v = d4[i];
        const int base = i * 4;
        if (v.x <= thr) { int p = atomicAdd(&s_cnt, 1); if (p < CAP) scand[p] = (unsigned short)(base + 0); }
        if (v.y <= thr) { int p = atomicAdd(&s_cnt, 1); if (p < CAP) scand[p] = (unsigned short)(base + 1); }
        if (v.z <= thr) { int p = atomicAdd(&s_cnt, 1); if (p < CAP) scand[p] = (unsigned short)(base + 2); }
        if (v.w <= thr) { int p = atomicAdd(&s_cnt, 1); if (p < CAP) scand[p] = (unsigned short)(base + 3); }
    }
    __syncthreads();
    const int cnt = (s_cnt < CAP) ? s_cnt : CAP;

    // ---- pass 4: exact fp32 rescore (ascending-k single-FMA chain) ----
    const float x2row = g_x2[row];
    for (int j = t; j < cnt; j += SEL_THREADS) {
        const int m = scand[j];
        const float4* b4 = reinterpret_cast<const float4*>(B + (size_t)m * DIM);
        float acc = 0.f;
        float4 cur = __ldg(b4);
#pragma unroll 4
        for (int i = 0; i < DIM / 4; i++) {
            float4 nxt = make_float4(0.f, 0.f, 0.f, 0.f);
            if (i + 1 < DIM / 4) nxt = __ldg(b4 + i + 1);
            float4 av = *reinterpret_cast<const float4*>(&s_arow[4 * i]);
            acc = __fmaf_rn(av.x, cur.x, acc);
            acc = __fmaf_rn(av.y, cur.y, acc);
            acc = __fmaf_rn(av.z, cur.z, acc);
            acc = __fmaf_rn(av.w, cur.w, acc);
            cur = nxt;
        }
        float tt = __fadd_rn(x2row, g_y2[m]);
        float uu = __fmul_rn(2.0f, acc);
        scex[j] = __fadd_rn(tt, -uu);
    }
    __syncthreads();

    // ---- pass 5: rank-select 20 by (exact asc, idx asc) ----
    for (int j = t; j < cnt; j += SEL_THREADS) {
        const float v = scex[j]; const int id = scand[j];
        int rk = 0;
        for (int q = 0; q < cnt; q++)
            rk += (scex[q] < v || (scex[q] == v && (int)scand[q] < id)) ? 1 : 0;
        if (rk < TOPK) { s20v[rk] = v; s20i[rk] = id; }
    }
    __syncthreads();

    // ---- pass 6: fp64 exact distances + anti-exact tie refine ----
    if (t < 32) {
        for (int j = 0; j < TOPK; j++) {
            const float* b = B + (size_t)s20i[j] * DIM;
            double s = 0.0;
            for (int k = t; k < DIM; k += 32) {
                double diff = (double)s_arow[k] - (double)b[k];
                s += diff * diff;
            }
#pragma unroll
            for (int o = 16; o > 0; o >>= 1)
                s += __shfl_down_sync(0xFFFFFFFFu, s, o);
            if (t == 0) s20d[j] = s;
            __syncwarp();
        }
    }
    __syncthreads();

    if (t == 0) {
        // stable insertion sort by (fp32 asc, fp64 exact DESC, idx asc)
        for (int i = 1; i < TOPK; i++) {
            float v = s20v[i]; double e = s20d[i]; int id = s20i[i];
            int j = i - 1;
            while (j >= 0 && (s20v[j] > v ||
                   (s20v[j] == v && (s20d[j] < e ||
                    (s20d[j] == e && s20i[j] > id))))) {
                s20v[j + 1] = s20v[j]; s20d[j + 1] = s20d[j]; s20i[j + 1] = s20i[j];
                --j;
            }
            s20v[j + 1] = v; s20d[j + 1] = e; s20i[j + 1] = id;
        }
        for (int i = 0; i < TOPK; i++) g_topk[row * TOPK + i] = s20i[i];
    }
}

// ---------------------------------------------------------------------------
// Kernel 4: gather selected query rows.
// ---------------------------------------------------------------------------
__global__ void gather_kernel(const float* __restrict__ q, float* __restrict__ out) {
    const int pair = blockIdx.x;
    const int idx  = g_topk[pair];
    const float4* src = reinterpret_cast<const float4*>(q + (size_t)idx * DIM);
    float4* dst = reinterpret_cast<float4*>(out + (size_t)pair * DIM);
    dst[threadIdx.x] = src[threadIdx.x];
}

// ---------------------------------------------------------------------------
// Kernel 5: accuracy scalar.
// ---------------------------------------------------------------------------
__global__ void acc_kernel(float* __restrict__ out, int out_size) {
    __shared__ int cnt[256];
    const int t = threadIdx.x;
    int c = 0;
    for (int j = t; j < NSUP * TOPK; j += 256) {
        int row = j / TOPK;
        int idx = g_topk[j];
        c += ((idx / QSHOT) == (row / KSHOT)) ? 1 : 0;
    }
    cnt[t] = c;
    __syncthreads();
    for (int s = 128; s > 0; s >>= 1) { if (t < s) cnt[t] += cnt[t + s]; __syncthreads(); }
    if (t == 0) {
        const int total = NSUP * TOPK * DIM;
        if (out_size > total)
            out[total] = __fdiv_rn((float)cnt[0], (float)(NSUP * TOPK));
    }
}

// ---------------------------------------------------------------------------
extern "C" void kernel_launch(void* const* d_in, const int* in_sizes, int n_in,
                              void* d_out, int out_size) {
    const float* support = (const float*)d_in[0];
    const float* query   = (const float*)d_in[1];
    if (n_in >= 2 && in_sizes[0] != NSUP * DIM) {
        support = (const float*)d_in[1];
        query   = (const float*)d_in[0];
    }
    float* out = (float*)d_out;

    rownorm_kernel<true ><<<NSUP / 8, 256>>>(support, NSUP);
    rownorm_kernel<false><<<NQRY / 8, 256>>>(query,   NQRY);
    {
        dim3 grid(NQRY / 128, NSUP / 128);   // (256, 8)
        approx_gemm_kernel<<<grid, 256>>>(support, query);
    }
    select_kernel<<<NSUP, SEL_THREADS>>>(support, query);
    gather_kernel<<<NSUP * TOPK, DIM / 4>>>(query, out);
    acc_kernel<<<1, 256>>>(out, out_size);
}